// round 8
// baseline (speedup 1.0000x reference)
#include <cuda_runtime.h>
#include <cstdint>
#include <cstddef>

typedef unsigned long long u64;

#define L_TOT 4096
#define NN    64
#define TCH   16
#define NCH   256
#define NTHR  512

// ---------------- scratch (device globals; no runtime allocation) ----------------
__device__ __align__(256) float g_At[L_TOT * NN * NN];     // g_At[t*4096 + k*64 + i] = A[t][i][k]
__device__ __align__(256) float g_S[9][NCH * NN * 128];    // scan round buffers [Y|M]
__device__ u64 g_flag[NCH];                                // per-block round-completion flags
__device__ u64 g_gen;                                      // launch generation (monotonic)

// ---------------- f32x2 helpers ----------------
__device__ __forceinline__ u64 pk2(float lo, float hi){
  u64 r; asm("mov.b64 %0, {%1,%2};" : "=l"(r) : "f"(lo), "f"(hi)); return r;
}
__device__ __forceinline__ u64 dup2(float v){
  u64 r; asm("mov.b64 %0, {%1,%1};" : "=l"(r) : "f"(v)); return r;
}
__device__ __forceinline__ void fma2(u64 &d, u64 a, u64 b){
  asm("fma.rn.f32x2 %0, %1, %2, %0;" : "+l"(d) : "l"(a), "l"(b));
}
__device__ __forceinline__ void add2(u64 &d, u64 a){
  asm("add.rn.f32x2 %0, %0, %1;" : "+l"(d) : "l"(a));
}
__device__ __forceinline__ void unpk2(u64 v, float &lo, float &hi){
  asm("mov.b64 {%0,%1}, %2;" : "=f"(lo), "=f"(hi) : "l"(v));
}

// ================= prep: transpose every A[t] (64x64) into g_At =================
__global__ void prep_kernel(const float* __restrict__ A){
  __shared__ float s[64 * 65];
  const int t = blockIdx.x;
  const float* src = A + (size_t)t * 4096;
  float* dst = g_At + (size_t)t * 4096;
  for (int idx = threadIdx.x; idx < 1024; idx += 256){
    int i = idx >> 4, k0 = (idx & 15) << 2;
    float4 v = *(const float4*)(src + i * 64 + k0);
    float* p = s + i * 65 + k0;
    p[0] = v.x; p[1] = v.y; p[2] = v.z; p[3] = v.w;
  }
  __syncthreads();
  for (int idx = threadIdx.x; idx < 1024; idx += 256){
    int k = idx >> 4, i0 = (idx & 15) << 2;
    float4 v;
    v.x = s[(i0 + 0) * 65 + k];
    v.y = s[(i0 + 1) * 65 + k];
    v.z = s[(i0 + 2) * 65 + k];
    v.w = s[(i0 + 3) * 65 + k];
    *(float4*)(dst + k * 64 + i0) = v;
  }
}

// ================= pass1: per-chunk affine map W = [Y | M] =================
// 16 warps; warp w owns rows {2w,2w+1} and {62-2w,63-2w}: 264 fma2/step each.
__global__ void __launch_bounds__(NTHR, 2)
pass1_kernel(const float* __restrict__ inp, const float* __restrict__ Bst){
  extern __shared__ float sm[];
  float* Atr = sm;                     // [2][64][68]  Atr[b][k*68+i] = A[t][i][k]
  float* Wb  = Atr + 2 * 64 * 68;      // [2][64][132]
  float* sIB = Wb + 2 * 64 * 132;      // [2][128]  [0..63]=inp, [64..127]=B

  const int c = blockIdx.x, tid = threadIdx.x;
  const int w = tid >> 5, lane = tid & 31;
  const int lo0 = w << 1;              // low row pair
  const int hi0 = 62 - (w << 1);       // high row pair
  const int klo = lo0 + 2;             // k < klo: both pairs
  const int khi = 64 - lo0;            // k < khi: high pair
  const int c0  = lane << 2;

  // A-tile staging: 1024 float4 slots over 512 threads = 2 each
  int ks[2], js[2];
#pragma unroll
  for (int q = 0; q < 2; ++q){ int s = tid + q * NTHR; ks[q] = s >> 4; js[q] = (s & 15) << 2; }

  for (int idx = tid; idx < 2 * 64 * 132; idx += NTHR) Wb[idx] = 0.0f;
  __syncthreads();
  if (tid < 64) Wb[tid * 132 + 64 + tid] = 1.0f;   // M = I in buffer 0

  const int t0 = c * TCH;
  {
    const float* Ap = g_At + (size_t)t0 * 4096;
#pragma unroll
    for (int q = 0; q < 2; ++q)
      *(float4*)(Atr + ks[q] * 68 + js[q]) = *(const float4*)(Ap + ks[q] * 64 + js[q]);
    if (tid < 64)       sIB[tid] = inp[(size_t)t0 * 64 + tid];
    else if (tid < 128) sIB[tid] = Bst[(size_t)t0 * 64 + (tid - 64)];
  }
  float4 pA[2]; float pIB = 0.0f;
  {
    const float* An = g_At + (size_t)(t0 + 1) * 4096;
#pragma unroll
    for (int q = 0; q < 2; ++q) pA[q] = *(const float4*)(An + ks[q] * 64 + js[q]);
    if (tid < 64)       pIB = inp[(size_t)(t0 + 1) * 64 + tid];
    else if (tid < 128) pIB = Bst[(size_t)(t0 + 1) * 64 + (tid - 64)];
  }
  __syncthreads();

  int cur = 0;
  for (int s = 0; s < TCH; ++s){
    const int ab = s & 1;
    const float* At  = Atr + ab * (64 * 68);
    const float* ib  = sIB + ab * 128;
    const float* Win = Wb + cur * (64 * 132);
    float*       Wout= Wb + (cur ^ 1) * (64 * 132);

    if (s + 1 < TCH){
      float* Ad = Atr + (ab ^ 1) * (64 * 68);
#pragma unroll
      for (int q = 0; q < 2; ++q) *(float4*)(Ad + ks[q] * 68 + js[q]) = pA[q];
      if (tid < 128) sIB[(ab ^ 1) * 128 + tid] = pIB;
    }
    if (s + 2 < TCH){
      const float* An = g_At + (size_t)(t0 + s + 2) * 4096;
#pragma unroll
      for (int q = 0; q < 2; ++q) pA[q] = *(const float4*)(An + ks[q] * 64 + js[q]);
      if (tid < 64)       pIB = inp[(size_t)(t0 + s + 2) * 64 + tid];
      else if (tid < 128) pIB = Bst[(size_t)(t0 + s + 2) * 64 + (tid - 64)];
    }

    u64 accL[2][2], accH[2][2];
#pragma unroll
    for (int r = 0; r < 2; ++r){ accL[r][0]=0; accL[r][1]=0; accH[r][0]=0; accH[r][1]=0; }

#pragma unroll 2
    for (int k = 0; k < klo; ++k){
      float2 avL = *(const float2*)(At + k * 68 + lo0);
      float2 avH = *(const float2*)(At + k * 68 + hi0);
      ulonglong2 wv = *(const ulonglong2*)(Win + k * 132 + c0);
      u64 b;
      b = dup2(avL.x); fma2(accL[0][0], b, wv.x); fma2(accL[0][1], b, wv.y);
      b = dup2(avL.y); fma2(accL[1][0], b, wv.x); fma2(accL[1][1], b, wv.y);
      b = dup2(avH.x); fma2(accH[0][0], b, wv.x); fma2(accH[0][1], b, wv.y);
      b = dup2(avH.y); fma2(accH[1][0], b, wv.x); fma2(accH[1][1], b, wv.y);
    }
#pragma unroll 4
    for (int k = klo; k < khi; ++k){
      float2 avH = *(const float2*)(At + k * 68 + hi0);
      ulonglong2 wv = *(const ulonglong2*)(Win + k * 132 + c0);
      u64 b;
      b = dup2(avH.x); fma2(accH[0][0], b, wv.x); fma2(accH[0][1], b, wv.y);
      b = dup2(avH.y); fma2(accH[1][0], b, wv.x); fma2(accH[1][1], b, wv.y);
    }

    if (c0 < 64){   // rank-1 input injection on the Y half
      u64 ipa = pk2(ib[c0],     ib[c0 + 1]);
      u64 ipb = pk2(ib[c0 + 2], ib[c0 + 3]);
#pragma unroll
      for (int r = 0; r < 2; ++r){
        u64 q;
        q = dup2(ib[64 + lo0 + r]); fma2(accL[r][0], q, ipa); fma2(accL[r][1], q, ipb);
        q = dup2(ib[64 + hi0 + r]); fma2(accH[r][0], q, ipa); fma2(accH[r][1], q, ipb);
      }
    }

#pragma unroll
    for (int r = 0; r < 2; ++r){
      ulonglong2 v;
      v.x = accL[r][0]; v.y = accL[r][1]; *(ulonglong2*)(Wout + (lo0 + r) * 132 + c0) = v;
      v.x = accH[r][0]; v.y = accH[r][1]; *(ulonglong2*)(Wout + (hi0 + r) * 132 + c0) = v;
    }
    __syncthreads();
    cur ^= 1;
  }

  const float* Wf = Wb + cur * (64 * 132);
  float* dst = g_S[0] + (size_t)c * 8192;
  for (int idx = tid; idx < 2048; idx += NTHR){
    int n = idx >> 5, q = (idx & 31) << 2;
    *(float4*)(dst + n * 128 + q) = *(const float4*)(Wf + n * 132 + q);
  }
}

// ================= scan_all: all 8 Kogge-Stone rounds in ONE launch =================
__global__ void __launch_bounds__(NTHR, 2)
scan_all_kernel(){
  extern __shared__ float sm[];
  float* Mtr  = sm;                 // [64][68]  Mtr[k*68+i] = M_later[i][k]
  float* Wbuf = Mtr + 64 * 68;      // [64][132] earlier [Y1|M1]
  float* Y2   = Wbuf + 64 * 132;    // [64][68]  later Y

  const int c = blockIdx.x, tid = threadIdx.x;
  const int w = tid >> 5, lane = tid & 31;
  const int lo0 = w << 1, hi0 = 62 - (w << 1);
  const int klo = lo0 + 2, khi = 64 - lo0;
  const int c0  = lane << 2;
  const u64 gen = (*(volatile u64*)&g_gen) * 9ULL;

  for (int r = 1; r <= 8; ++r){
    const int d = 1 << (r - 1);
    const float* src = g_S[r - 1];
    float*       dst = g_S[r];

    if (c < d){
      const float* s = src + (size_t)c * 8192;
      float*       o = dst + (size_t)c * 8192;
      for (int idx = tid; idx < 2048; idx += NTHR)
        *(float4*)(o + idx * 4) = *(const float4*)(s + idx * 4);
    } else {
      if (r > 1){
        if (tid == 0){
          const u64 target = gen + (u64)(r - 1);
          while (*(volatile u64*)&g_flag[c - d] < target) { }
        }
      }
      __syncthreads();
      __threadfence();

      const float* later   = src + (size_t)c * 8192;
      const float* earlier = src + (size_t)(c - d) * 8192;

      for (int idx = tid; idx < 4096; idx += NTHR){
        int i = idx >> 6, k = idx & 63;
        Mtr[k * 68 + i] = later[i * 128 + 64 + k];
      }
      for (int idx = tid; idx < 1024; idx += NTHR){
        int i = idx >> 4, q = (idx & 15) << 2;
        *(float4*)(Y2 + i * 68 + q) = *(const float4*)(later + i * 128 + q);
      }
      for (int idx = tid; idx < 2048; idx += NTHR){
        int n = idx >> 5, q = (idx & 31) << 2;
        *(float4*)(Wbuf + n * 132 + q) = *(const float4*)(earlier + n * 128 + q);
      }
      __syncthreads();

      u64 accL[2][2], accH[2][2];
#pragma unroll
      for (int rr = 0; rr < 2; ++rr){ accL[rr][0]=0; accL[rr][1]=0; accH[rr][0]=0; accH[rr][1]=0; }

#pragma unroll 2
      for (int k = 0; k < klo; ++k){
        float2 avL = *(const float2*)(Mtr + k * 68 + lo0);
        float2 avH = *(const float2*)(Mtr + k * 68 + hi0);
        ulonglong2 wv = *(const ulonglong2*)(Wbuf + k * 132 + c0);
        u64 b;
        b = dup2(avL.x); fma2(accL[0][0], b, wv.x); fma2(accL[0][1], b, wv.y);
        b = dup2(avL.y); fma2(accL[1][0], b, wv.x); fma2(accL[1][1], b, wv.y);
        b = dup2(avH.x); fma2(accH[0][0], b, wv.x); fma2(accH[0][1], b, wv.y);
        b = dup2(avH.y); fma2(accH[1][0], b, wv.x); fma2(accH[1][1], b, wv.y);
      }
#pragma unroll 4
      for (int k = klo; k < khi; ++k){
        float2 avH = *(const float2*)(Mtr + k * 68 + hi0);
        ulonglong2 wv = *(const ulonglong2*)(Wbuf + k * 132 + c0);
        u64 b;
        b = dup2(avH.x); fma2(accH[0][0], b, wv.x); fma2(accH[0][1], b, wv.y);
        b = dup2(avH.y); fma2(accH[1][0], b, wv.x); fma2(accH[1][1], b, wv.y);
      }

      if (c0 < 64){
#pragma unroll
        for (int rr = 0; rr < 2; ++rr){
          ulonglong2 yv;
          yv = *(const ulonglong2*)(Y2 + (lo0 + rr) * 68 + c0); add2(accL[rr][0], yv.x); add2(accL[rr][1], yv.y);
          yv = *(const ulonglong2*)(Y2 + (hi0 + rr) * 68 + c0); add2(accH[rr][0], yv.x); add2(accH[rr][1], yv.y);
        }
      }

      float* o = dst + (size_t)c * 8192;
#pragma unroll
      for (int rr = 0; rr < 2; ++rr){
        ulonglong2 v;
        v.x = accL[rr][0]; v.y = accL[rr][1]; *(ulonglong2*)(o + (lo0 + rr) * 128 + c0) = v;
        v.x = accH[rr][0]; v.y = accH[rr][1]; *(ulonglong2*)(o + (hi0 + rr) * 128 + c0) = v;
      }
    }

    __threadfence();
    __syncthreads();
    if (tid == 0) *(volatile u64*)&g_flag[c] = gen + (u64)r;
  }
}

__global__ void bump_gen_kernel(){ g_gen += 1ULL; }

// ================= pass3: re-run recurrence with carries, write out =================
__global__ void __launch_bounds__(NTHR, 2)
pass3_kernel(const float* __restrict__ inp, const float* __restrict__ Bst,
             float* __restrict__ out){
  extern __shared__ float sm[];
  float* Atr = sm;                     // [2][64][68]
  float* Xb  = Atr + 2 * 64 * 68;      // [2][64][68]   state X[n][b]
  float* sIB = Xb + 2 * 64 * 68;       // [2][128]

  const int c = blockIdx.x, tid = threadIdx.x;
  const int w = tid >> 5, lane = tid & 31;
  const int lo0 = w << 1, hi0 = 62 - (w << 1);
  const int klo = lo0 + 2, khi = 64 - lo0;
  const int c0  = lane << 1;

  int ks[2], js[2];
#pragma unroll
  for (int q = 0; q < 2; ++q){ int s = tid + q * NTHR; ks[q] = s >> 4; js[q] = (s & 15) << 2; }

  // init X = Y of scanned prefix (chunk c-1), or 0 for chunk 0
  if (c == 0){
    for (int idx = tid; idx < 64 * 68; idx += NTHR) Xb[idx] = 0.0f;
  } else {
    const float* Yp = g_S[8] + (size_t)(c - 1) * 8192;
    for (int idx = tid; idx < 1024; idx += NTHR){
      int n = idx >> 4, q = (idx & 15) << 2;
      *(float4*)(Xb + n * 68 + q) = *(const float4*)(Yp + n * 128 + q);
    }
  }

  const int t0 = c * TCH;
  {
    const float* Ap = g_At + (size_t)t0 * 4096;
#pragma unroll
    for (int q = 0; q < 2; ++q)
      *(float4*)(Atr + ks[q] * 68 + js[q]) = *(const float4*)(Ap + ks[q] * 64 + js[q]);
    if (tid < 64)       sIB[tid] = inp[(size_t)t0 * 64 + tid];
    else if (tid < 128) sIB[tid] = Bst[(size_t)t0 * 64 + (tid - 64)];
  }
  float4 pA[2]; float pIB = 0.0f;
  {
    const float* An = g_At + (size_t)(t0 + 1) * 4096;
#pragma unroll
    for (int q = 0; q < 2; ++q) pA[q] = *(const float4*)(An + ks[q] * 64 + js[q]);
    if (tid < 64)       pIB = inp[(size_t)(t0 + 1) * 64 + tid];
    else if (tid < 128) pIB = Bst[(size_t)(t0 + 1) * 64 + (tid - 64)];
  }
  __syncthreads();

  int cur = 0;
  for (int s = 0; s < TCH; ++s){
    const int ab = s & 1;
    const float* At  = Atr + ab * (64 * 68);
    const float* ib  = sIB + ab * 128;
    const float* Xin = Xb + cur * (64 * 68);
    float*       Xout= Xb + (cur ^ 1) * (64 * 68);

    if (s + 1 < TCH){
      float* Ad = Atr + (ab ^ 1) * (64 * 68);
#pragma unroll
      for (int q = 0; q < 2; ++q) *(float4*)(Ad + ks[q] * 68 + js[q]) = pA[q];
      if (tid < 128) sIB[(ab ^ 1) * 128 + tid] = pIB;
    }
    if (s + 2 < TCH){
      const float* An = g_At + (size_t)(t0 + s + 2) * 4096;
#pragma unroll
      for (int q = 0; q < 2; ++q) pA[q] = *(const float4*)(An + ks[q] * 64 + js[q]);
      if (tid < 64)       pIB = inp[(size_t)(t0 + s + 2) * 64 + tid];
      else if (tid < 128) pIB = Bst[(size_t)(t0 + s + 2) * 64 + (tid - 64)];
    }

    u64 aL[2], aH[2];
#pragma unroll
    for (int r = 0; r < 2; ++r){ aL[r] = 0; aH[r] = 0; }

#pragma unroll 2
    for (int k = 0; k < klo; ++k){
      float2 avL = *(const float2*)(At + k * 68 + lo0);
      float2 avH = *(const float2*)(At + k * 68 + hi0);
      u64 xv = *(const u64*)(Xin + k * 68 + c0);
      fma2(aL[0], dup2(avL.x), xv);
      fma2(aL[1], dup2(avL.y), xv);
      fma2(aH[0], dup2(avH.x), xv);
      fma2(aH[1], dup2(avH.y), xv);
    }
#pragma unroll 4
    for (int k = klo; k < khi; ++k){
      float2 avH = *(const float2*)(At + k * 68 + hi0);
      u64 xv = *(const u64*)(Xin + k * 68 + c0);
      fma2(aH[0], dup2(avH.x), xv);
      fma2(aH[1], dup2(avH.y), xv);
    }
    {
      u64 ip = pk2(ib[c0], ib[c0 + 1]);
#pragma unroll
      for (int r = 0; r < 2; ++r){
        fma2(aL[r], dup2(ib[64 + lo0 + r]), ip);
        fma2(aH[r], dup2(ib[64 + hi0 + r]), ip);
      }
    }
#pragma unroll
    for (int r = 0; r < 2; ++r){
      *(u64*)(Xout + (lo0 + r) * 68 + c0) = aL[r];
      *(u64*)(Xout + (hi0 + r) * 68 + c0) = aH[r];
    }

    // direct register -> gmem output: out[t][b][n] = X[n][b]
    float l0, h0, l1, h1;
    float* base = out + (size_t)(t0 + s) * 4096 + (size_t)c0 * 64;
    float2 v;
    unpk2(aL[0], l0, h0); unpk2(aL[1], l1, h1);
    v.x = l0; v.y = l1; *(float2*)(base + lo0)      = v;
    v.x = h0; v.y = h1; *(float2*)(base + 64 + lo0) = v;
    unpk2(aH[0], l0, h0); unpk2(aH[1], l1, h1);
    v.x = l0; v.y = l1; *(float2*)(base + hi0)      = v;
    v.x = h0; v.y = h1; *(float2*)(base + 64 + hi0) = v;

    __syncthreads();
    cur ^= 1;
  }
}

// ================= host =================
extern "C" void kernel_launch(void* const* d_in, const int* in_sizes, int n_in,
                              void* d_out, int out_size){
  const float* inp = (const float*)d_in[0];   // (L, B)
  const float* A   = (const float*)d_in[1];   // (L, N, N)
  const float* Bst = (const float*)d_in[2];   // (L, N)
  float* out = (float*)d_out;                 // (L, B, N)

  const int SMEM1 = (2 * 64 * 68 + 2 * 64 * 132 + 256) * 4;  // 103424
  const int SMEMS = (64 * 68 + 64 * 132 + 64 * 68) * 4;      // 68608
  const int SMEM3 = (2 * 64 * 68 + 2 * 64 * 68 + 256) * 4;   // 70656

  cudaFuncSetAttribute(pass1_kernel,    cudaFuncAttributeMaxDynamicSharedMemorySize, SMEM1);
  cudaFuncSetAttribute(scan_all_kernel, cudaFuncAttributeMaxDynamicSharedMemorySize, SMEMS);
  cudaFuncSetAttribute(pass3_kernel,    cudaFuncAttributeMaxDynamicSharedMemorySize, SMEM3);

  prep_kernel<<<L_TOT, 256>>>(A);
  pass1_kernel<<<NCH, NTHR, SMEM1>>>(inp, Bst);
  scan_all_kernel<<<NCH, NTHR, SMEMS>>>();
  pass3_kernel<<<NCH, NTHR, SMEM3>>>(inp, Bst, out);
  bump_gen_kernel<<<1, 1>>>();
}